// round 2
// baseline (speedup 1.0000x reference)
#include <cuda_runtime.h>

#define PLANE (128*128)
#define VOL (128*128*128)

// Scratch (device globals — no allocation allowed)
__device__ float g_H[8*VOL];   // 64 MB
__device__ float g_A[8*VOL];   // 64 MB
__device__ float g_W[27*VOL];  // 226 MB adaptive weight field
__device__ float g_F[VOL];     // 8 MB single-channel ping buffer

// ---- packed f32x2 helpers (FFMA2 is PTX-only on sm_103a) ----
__device__ __forceinline__ unsigned long long pack2(float lo, float hi){
  unsigned long long r;
  asm("mov.b64 %0, {%1, %2};" : "=l"(r) : "f"(lo), "f"(hi));
  return r;
}
__device__ __forceinline__ void unpack2(float& lo, float& hi, unsigned long long v){
  asm("mov.b64 {%0, %1}, %2;" : "=f"(lo), "=f"(hi) : "l"(v));
}
__device__ __forceinline__ void fma2(unsigned long long& d, unsigned long long a, unsigned long long b){
  asm("fma.rn.f32x2 %0, %1, %2, %0;" : "+l"(d) : "l"(a), "l"(b));
}

// ============================================================================
// Generic 3x3x3 conv, CIN=8, SAME zero padding, channel-planar layout.
// One CTA per (d,h) row; 128 threads = 128 w-positions.
// Output channels accumulated as f32x2 pairs; weights pre-packed in SMEM.
// ============================================================================
template<int COUT, bool RELU, bool NORM>
__global__ void __launch_bounds__(128)
conv3d_k(const float* __restrict__ x, const float* __restrict__ wgt,
         const float* __restrict__ bias, float* __restrict__ out)
{
  constexpr int CP = (COUT + 1) / 2;
  __shared__ unsigned long long wp[8*27*CP];
  __shared__ float tile[9*132];
  const int tid = threadIdx.x;
  const int h = blockIdx.x, d = blockIdx.y;

  // pack weights: wp[(ci*27+t)*CP+p] = { W[2p][ci][t], W[2p+1][ci][t] }
  for (int i = tid; i < 8*27*CP; i += 128){
    int p = i % CP; int rest = i / CP; int t = rest % 27; int ci = rest / 27;
    float lo = wgt[(2*p*8 + ci)*27 + t];
    float hi = (2*p+1 < COUT) ? wgt[((2*p+1)*8 + ci)*27 + t] : 0.f;
    wp[i] = pack2(lo, hi);
  }

  unsigned long long acc[CP];
  #pragma unroll
  for (int p = 0; p < CP; p++){
    float blo = bias ? bias[2*p] : 0.f;
    float bhi = (bias && (2*p+1 < COUT)) ? bias[2*p+1] : 0.f;
    acc[p] = pack2(blo, bhi);
  }

  for (int ci = 0; ci < 8; ci++){
    __syncthreads();                      // prev compute done (and wp ready on ci=0)
    for (int i = tid; i < 9*130; i += 128){
      int r = i / 130, c = i % 130;
      int dd = d + r/3 - 1;
      int hh = h + r%3 - 1;
      int ww = c - 1;
      float v = 0.f;
      if ((unsigned)dd < 128u && (unsigned)hh < 128u && (unsigned)ww < 128u)
        v = x[ci*VOL + dd*PLANE + hh*128 + ww];
      tile[r*132 + c] = v;
    }
    __syncthreads();
    #pragma unroll
    for (int r = 0; r < 9; r++){
      float v0 = tile[r*132+tid], v1 = tile[r*132+tid+1], v2 = tile[r*132+tid+2];
      unsigned long long vv0 = pack2(v0,v0), vv1 = pack2(v1,v1), vv2 = pack2(v2,v2);
      const unsigned long long* wr = &wp[(ci*27 + r*3)*CP];
      #pragma unroll
      for (int p = 0; p < CP; p++) fma2(acc[p], vv0, wr[p]);
      #pragma unroll
      for (int p = 0; p < CP; p++) fma2(acc[p], vv1, wr[CP+p]);
      #pragma unroll
      for (int p = 0; p < CP; p++) fma2(acc[p], vv2, wr[2*CP+p]);
    }
  }

  float res[2*CP];
  #pragma unroll
  for (int p = 0; p < CP; p++) unpack2(res[2*p], res[2*p+1], acc[p]);

  if (RELU){
    #pragma unroll
    for (int c = 0; c < COUT; c++) res[c] = fmaxf(res[c], 0.f);
  }
  const int idx = d*PLANE + h*128 + tid;
  if (NORM){
    float s = 0.f;
    #pragma unroll
    for (int c = 0; c < COUT; c++) s += fabsf(res[c]);
    s = fmaxf(s, 1e-12f);
    float inv = 1.f / s;
    #pragma unroll
    for (int c = 0; c < COUT; c++) out[c*VOL + idx] = res[c]*inv;
  } else {
    #pragma unroll
    for (int c = 0; c < COUT; c++) out[c*VOL + idx] = res[c];
  }
}

// ============================================================================
// Adaptive conv: out[c,v] = sum_t w27[t,v] * x[c, nbr_t(v)].
// 27 per-voxel weights kept in registers, reused across all C channels.
// ============================================================================
template<int C, bool TANH>
__global__ void __launch_bounds__(128)
adapt_k(const float* __restrict__ x, const float* __restrict__ w27,
        float* __restrict__ out)
{
  __shared__ float tile[9*132];
  const int tid = threadIdx.x;
  const int h = blockIdx.x, d = blockIdx.y;
  const int idx = d*PLANE + h*128 + tid;

  float wv[27];
  #pragma unroll
  for (int t = 0; t < 27; t++) wv[t] = w27[t*VOL + idx];

  for (int c = 0; c < C; c++){
    __syncthreads();
    for (int i = tid; i < 9*130; i += 128){
      int r = i / 130, cc = i % 130;
      int dd = d + r/3 - 1, hh = h + r%3 - 1, ww = cc - 1;
      float v = 0.f;
      if ((unsigned)dd < 128u && (unsigned)hh < 128u && (unsigned)ww < 128u)
        v = x[c*VOL + dd*PLANE + hh*128 + ww];
      tile[r*132 + cc] = v;
    }
    __syncthreads();
    float acc = 0.f;
    #pragma unroll
    for (int r = 0; r < 9; r++){
      acc = fmaf(wv[r*3+0], tile[r*132+tid  ], acc);
      acc = fmaf(wv[r*3+1], tile[r*132+tid+1], acc);
      acc = fmaf(wv[r*3+2], tile[r*132+tid+2], acc);
    }
    out[c*VOL + idx] = TANH ? tanhf(acc) : acc;
  }
}

extern "C" void kernel_launch(void* const* d_in, const int* in_sizes, int n_in,
                              void* d_out, int out_size)
{
  const float* x    = (const float*)d_in[0];
  const float* a1w1 = (const float*)d_in[1];
  const float* a1b1 = (const float*)d_in[2];
  const float* a1w2 = (const float*)d_in[3];
  const float* a2w1 = (const float*)d_in[4];
  const float* a2b1 = (const float*)d_in[5];
  const float* a2w2 = (const float*)d_in[6];
  const float* a3w1 = (const float*)d_in[7];
  const float* a3b1 = (const float*)d_in[8];
  const float* a3w2 = (const float*)d_in[9];
  const float* midw = (const float*)d_in[10];
  const float* midb = (const float*)d_in[11];
  const float* outw = (const float*)d_in[12];
  const float* outb = (const float*)d_in[13];
  float* y = (float*)d_out;

  float *H, *A, *W, *F;
  cudaGetSymbolAddress((void**)&H, g_H);
  cudaGetSymbolAddress((void**)&A, g_A);
  cudaGetSymbolAddress((void**)&W, g_W);
  cudaGetSymbolAddress((void**)&F, g_F);

  dim3 g(128, 128), b(128);

  // ---- adaptive block 1 (input x) ----
  conv3d_k<8,  true,  false><<<g,b>>>(x, a1w1, a1b1, H);     // h1
  conv3d_k<27, false, true ><<<g,b>>>(H, a1w2, nullptr, W);  // w field
  adapt_k<8, false><<<g,b>>>(x, W, A);
  adapt_k<8, false><<<g,b>>>(A, W, H);
  adapt_k<8, false><<<g,b>>>(H, W, A);                       // block1 out = A

  // ---- mid conv ----
  conv3d_k<8, false, false><<<g,b>>>(A, midw, midb, H);      // mid = H

  // ---- adaptive block 2 (input mid) ----
  conv3d_k<8,  true,  false><<<g,b>>>(H, a2w1, a2b1, A);     // h2
  conv3d_k<27, false, true ><<<g,b>>>(A, a2w2, nullptr, W);
  adapt_k<8, false><<<g,b>>>(H, W, A);
  adapt_k<8, false><<<g,b>>>(A, W, H);
  adapt_k<8, false><<<g,b>>>(H, W, A);                       // mid2 = A

  // ---- out conv + adaptive block 3 (weights from mid2, data 1-channel) ----
  conv3d_k<1, false, false><<<g,b>>>(A, outw, outb, F);      // final (1ch)
  conv3d_k<8, true,  false><<<g,b>>>(A, a3w1, a3b1, H);      // h3 from mid2
  conv3d_k<27, false, true ><<<g,b>>>(H, a3w2, nullptr, W);
  adapt_k<1, false><<<g,b>>>(F, W, y);
  adapt_k<1, false><<<g,b>>>(y, W, F);
  adapt_k<1, true ><<<g,b>>>(F, W, y);                       // + tanh
}

// round 3
// speedup vs baseline: 2.0087x; 2.0087x over previous
#include <cuda_runtime.h>

#define PLANE (128*128)
#define VOL (128*128*128)

// Scratch (device globals — no allocation allowed)
__device__ float g_H[8*VOL];   // 64 MB
__device__ float g_A[8*VOL];   // 64 MB
__device__ float g_W[27*VOL];  // 226 MB adaptive weight field
__device__ float g_F[VOL];     // 8 MB single-channel ping buffer

// ---- packed f32x2 helpers (FFMA2 is PTX-only on sm_103a) ----
__device__ __forceinline__ unsigned long long pack2(float lo, float hi){
  unsigned long long r;
  asm("mov.b64 %0, {%1, %2};" : "=l"(r) : "f"(lo), "f"(hi));
  return r;
}
__device__ __forceinline__ void unpack2(float& lo, float& hi, unsigned long long v){
  asm("mov.b64 {%0, %1}, %2;" : "=f"(lo), "=f"(hi) : "l"(v));
}
__device__ __forceinline__ void fma2(unsigned long long& d, unsigned long long a, unsigned long long b){
  asm("fma.rn.f32x2 %0, %1, %2, %0;" : "+l"(d) : "l"(a), "l"(b));
}

// ============================================================================
// 3x3x3 conv, CIN=8, SAME zero padding, channel-planar layout.
// Direct predicated LDG with compile-time immediate offsets (no tile SMEM).
// 2 voxels per thread (h-pair) so each weight LDS.64 feeds two fma2.
// Grid: (64, 128) = (h/2, d); block 128 = w.
// ============================================================================
template<int COUT, bool RELU, bool NORM>
__global__ void __launch_bounds__(128)
conv3d_k(const float* __restrict__ x, const float* __restrict__ wgt,
         const float* __restrict__ bias, float* __restrict__ out)
{
  constexpr int CP = (COUT + 1) / 2;
  __shared__ unsigned long long wp[8*27*CP];
  const int tid = threadIdx.x;              // w
  const int h0 = 2*blockIdx.x;              // even h
  const int d  = blockIdx.y;

  // pack weights: wp[(ci*27+t)*CP+p] = { W[2p][ci][t], W[2p+1][ci][t] }
  for (int i = tid; i < 8*27*CP; i += 128){
    int p = i % CP; int rest = i / CP; int t = rest % 27; int ci = rest / 27;
    float lo = wgt[(2*p*8 + ci)*27 + t];
    float hi = (2*p+1 < COUT) ? wgt[((2*p+1)*8 + ci)*27 + t] : 0.f;
    wp[i] = pack2(lo, hi);
  }
  __syncthreads();

  unsigned long long acc0[CP], acc1[CP];
  #pragma unroll
  for (int p = 0; p < CP; p++){
    float blo = bias ? bias[2*p] : 0.f;
    float bhi = (bias && (2*p+1 < COUT)) ? bias[2*p+1] : 0.f;
    acc0[p] = pack2(blo, bhi);
    acc1[p] = acc0[p];
  }

  const int w = tid;
  const int base0 = d*PLANE + h0*128 + w;
  const bool pd[3]  = { d > 0,  true, d < 127 };
  const bool pw[3]  = { w > 0,  true, w < 127 };
  const bool ph0v[3] = { h0 > 0, true, true      };   // h0+1 <= 127 always
  const bool ph1v[3] = { true,   true, h0 < 126  };   // h0 >= 0 always

  #pragma unroll 1
  for (int ci = 0; ci < 8; ci++){
    const float* b0 = x + ci*VOL + base0;
    const unsigned long long* wr = wp + ci*27*CP;
    #pragma unroll
    for (int i = 0; i < 3; i++){
      #pragma unroll
      for (int j = 0; j < 3; j++){
        #pragma unroll
        for (int k = 0; k < 3; k++){
          const int OFF = (i-1)*PLANE + (j-1)*128 + (k-1);
          const bool pv = pd[i] && pw[k];
          float v0 = 0.f, v1 = 0.f;
          if (pv && ph0v[j]) v0 = __ldg(b0 + OFF);
          if (pv && ph1v[j]) v1 = __ldg(b0 + 128 + OFF);
          unsigned long long vv0 = pack2(v0, v0);
          unsigned long long vv1 = pack2(v1, v1);
          const unsigned long long* wt = wr + (i*9 + j*3 + k)*CP;
          #pragma unroll
          for (int p = 0; p < CP; p++){
            unsigned long long wv = wt[p];
            fma2(acc0[p], vv0, wv);
            fma2(acc1[p], vv1, wv);
          }
        }
      }
    }
  }

  float r0[2*CP], r1[2*CP];
  #pragma unroll
  for (int p = 0; p < CP; p++){
    unpack2(r0[2*p], r0[2*p+1], acc0[p]);
    unpack2(r1[2*p], r1[2*p+1], acc1[p]);
  }

  if (RELU){
    #pragma unroll
    for (int c = 0; c < COUT; c++){ r0[c] = fmaxf(r0[c], 0.f); r1[c] = fmaxf(r1[c], 0.f); }
  }
  if (NORM){
    float s0 = 0.f, s1 = 0.f;
    #pragma unroll
    for (int c = 0; c < COUT; c++){ s0 += fabsf(r0[c]); s1 += fabsf(r1[c]); }
    float i0 = 1.f / fmaxf(s0, 1e-12f);
    float i1 = 1.f / fmaxf(s1, 1e-12f);
    #pragma unroll
    for (int c = 0; c < COUT; c++){
      out[c*VOL + base0]       = r0[c]*i0;
      out[c*VOL + base0 + 128] = r1[c]*i1;
    }
  } else {
    #pragma unroll
    for (int c = 0; c < COUT; c++){
      out[c*VOL + base0]       = r0[c];
      out[c*VOL + base0 + 128] = r1[c];
    }
  }
}

// ============================================================================
// Adaptive conv: out[c,v] = sum_t w27[t,v] * x[c, nbr_t(v)].
// No SMEM: 27 per-voxel weights in registers (reused over all C channels),
// neighbors fetched with predicated LDG at compile-time immediate offsets.
// ============================================================================
template<int C, bool TANH>
__global__ void __launch_bounds__(256)
adapt_k(const float* __restrict__ x, const float* __restrict__ w27,
        float* __restrict__ out)
{
  const int idx = blockIdx.x*256 + threadIdx.x;
  const int d = idx >> 14;
  const int h = (idx >> 7) & 127;
  const int w = idx & 127;

  float wv[27];
  #pragma unroll
  for (int t = 0; t < 27; t++) wv[t] = __ldg(w27 + t*VOL + idx);

  const bool pd[3] = { d > 0, true, d < 127 };
  const bool ph[3] = { h > 0, true, h < 127 };
  const bool pw[3] = { w > 0, true, w < 127 };

  #pragma unroll 1
  for (int c = 0; c < C; c++){
    const float* b = x + c*VOL + idx;
    float acc = 0.f;
    #pragma unroll
    for (int i = 0; i < 3; i++){
      #pragma unroll
      for (int j = 0; j < 3; j++){
        #pragma unroll
        for (int k = 0; k < 3; k++){
          const int OFF = (i-1)*PLANE + (j-1)*128 + (k-1);
          float v = 0.f;
          if (pd[i] && ph[j] && pw[k]) v = __ldg(b + OFF);
          acc = fmaf(wv[i*9 + j*3 + k], v, acc);
        }
      }
    }
    out[c*VOL + idx] = TANH ? tanhf(acc) : acc;
  }
}

extern "C" void kernel_launch(void* const* d_in, const int* in_sizes, int n_in,
                              void* d_out, int out_size)
{
  const float* x    = (const float*)d_in[0];
  const float* a1w1 = (const float*)d_in[1];
  const float* a1b1 = (const float*)d_in[2];
  const float* a1w2 = (const float*)d_in[3];
  const float* a2w1 = (const float*)d_in[4];
  const float* a2b1 = (const float*)d_in[5];
  const float* a2w2 = (const float*)d_in[6];
  const float* a3w1 = (const float*)d_in[7];
  const float* a3b1 = (const float*)d_in[8];
  const float* a3w2 = (const float*)d_in[9];
  const float* midw = (const float*)d_in[10];
  const float* midb = (const float*)d_in[11];
  const float* outw = (const float*)d_in[12];
  const float* outb = (const float*)d_in[13];
  float* y = (float*)d_out;

  float *H, *A, *W, *F;
  cudaGetSymbolAddress((void**)&H, g_H);
  cudaGetSymbolAddress((void**)&A, g_A);
  cudaGetSymbolAddress((void**)&W, g_W);
  cudaGetSymbolAddress((void**)&F, g_F);

  dim3 gc(64, 128), bc(128);     // conv: h-pair x d, 128 w-threads
  dim3 ga(VOL/256), ba(256);     // adapt: linear

  // ---- adaptive block 1 (input x) ----
  conv3d_k<8,  true,  false><<<gc,bc>>>(x, a1w1, a1b1, H);     // h1
  conv3d_k<27, false, true ><<<gc,bc>>>(H, a1w2, nullptr, W);  // w field
  adapt_k<8, false><<<ga,ba>>>(x, W, A);
  adapt_k<8, false><<<ga,ba>>>(A, W, H);
  adapt_k<8, false><<<ga,ba>>>(H, W, A);                       // block1 out = A

  // ---- mid conv ----
  conv3d_k<8, false, false><<<gc,bc>>>(A, midw, midb, H);      // mid = H

  // ---- adaptive block 2 (input mid) ----
  conv3d_k<8,  true,  false><<<gc,bc>>>(H, a2w1, a2b1, A);     // h2
  conv3d_k<27, false, true ><<<gc,bc>>>(A, a2w2, nullptr, W);
  adapt_k<8, false><<<ga,ba>>>(H, W, A);
  adapt_k<8, false><<<ga,ba>>>(A, W, H);
  adapt_k<8, false><<<ga,ba>>>(H, W, A);                       // mid2 = A

  // ---- out conv + adaptive block 3 (weights from mid2, data 1-channel) ----
  conv3d_k<1, false, false><<<gc,bc>>>(A, outw, outb, F);      // final (1ch)
  conv3d_k<8, true,  false><<<gc,bc>>>(A, a3w1, a3b1, H);      // h3 from mid2
  conv3d_k<27, false, true ><<<gc,bc>>>(H, a3w2, nullptr, W);
  adapt_k<1, false><<<ga,ba>>>(F, W, y);
  adapt_k<1, false><<<ga,ba>>>(y, W, F);
  adapt_k<1, true ><<<ga,ba>>>(F, W, y);                       // + tanh
}